// round 15
// baseline (speedup 1.0000x reference)
#include <cuda_runtime.h>
#include <cuda_bf16.h>
#include <cuda_fp16.h>
#include <cstdint>
#include <math_constants.h>

constexpr int BATCH = 8;
constexpr int DIM   = 512;
constexpr int SEQ   = 2048;

// ---------------------------------------------------------------------------
// Scratch (device globals; no allocation allowed)
// ---------------------------------------------------------------------------
__device__ __align__(128) __nv_bfloat16 g_xt_hi[(size_t)BATCH * SEQ * DIM]; // [b][n][c]
__device__ __align__(128) __nv_bfloat16 g_xt_lo[(size_t)BATCH * SEQ * DIM];
__device__ __align__(128) __nv_bfloat16 g_w_hi[3][(size_t)DIM * DIM];      // [which][d][c]
__device__ __align__(128) __nv_bfloat16 g_w_lo[3][(size_t)DIM * DIM];
__device__ __align__(128) __nv_bfloat16 g_q_hi[(size_t)BATCH * SEQ * DIM]; // [b][n][d]
__device__ __align__(128) __nv_bfloat16 g_q_lo[(size_t)BATCH * SEQ * DIM];
__device__ __align__(128) __nv_bfloat16 g_k_hi[(size_t)BATCH * SEQ * DIM];
__device__ __align__(128) __nv_bfloat16 g_k_lo[(size_t)BATCH * SEQ * DIM];
__device__ __align__(128) __half        g_vt   [(size_t)BATCH * DIM * SEQ]; // [b][d][m] fp16
__device__ __align__(128) float         g_scores[(size_t)BATCH * SEQ * SEQ];
__device__ __align__(128) __half        g_p_hi[(size_t)BATCH * SEQ * SEQ]; // [b][n][m] fp16
__device__ __align__(128) __half        g_p_lo[(size_t)BATCH * SEQ * SEQ];

// ---------------------------------------------------------------------------
// Helpers
// ---------------------------------------------------------------------------
__device__ __forceinline__ uint32_t smem_to_u32(const void* p) {
    uint32_t a;
    asm("{ .reg .u64 t; cvta.to.shared.u64 t, %1; cvt.u32.u64 %0, t; }" : "=r"(a) : "l"(p));
    return a;
}
#define SWZ(x)   ((x) ^ (((x) >> 3) & 0x70))
#define SWZ64(x) ((x) ^ (((x) >> 3) & 0x30))

__device__ __forceinline__ void split2(float f, __nv_bfloat16& h, __nv_bfloat16& l) {
    h = __float2bfloat16(f);
    l = __float2bfloat16(f - __bfloat162float(h));
}
__device__ __forceinline__ uint32_t pack2(__nv_bfloat16 a, __nv_bfloat16 b) {
    __nv_bfloat162 t = __halves2bfloat162(a, b);
    return *reinterpret_cast<uint32_t*>(&t);
}
__device__ __forceinline__ void split2h(float f, __half& h, __half& l) {
    h = __float2half(f);
    l = __float2half(f - __half2float(h));
}
__device__ __forceinline__ uint32_t pack2h(__half a, __half b) {
    __half2 t = __halves2half2(a, b);
    return *reinterpret_cast<uint32_t*>(&t);
}

__device__ __forceinline__ void ldsm_x4(uint32_t* r, uint32_t addr) {
    asm volatile("ldmatrix.sync.aligned.m8n8.x4.shared.b16 {%0,%1,%2,%3}, [%4];"
        : "=r"(r[0]), "=r"(r[1]), "=r"(r[2]), "=r"(r[3]) : "r"(addr));
}
__device__ __forceinline__ void mma16816(float* c, const uint32_t* a, const uint32_t* b) {
    asm volatile(
        "mma.sync.aligned.m16n8k16.row.col.f32.bf16.bf16.f32 "
        "{%0,%1,%2,%3}, {%4,%5,%6,%7}, {%8,%9}, {%0,%1,%2,%3};"
        : "+f"(c[0]), "+f"(c[1]), "+f"(c[2]), "+f"(c[3])
        : "r"(a[0]), "r"(a[1]), "r"(a[2]), "r"(a[3]), "r"(b[0]), "r"(b[1]));
}
__device__ __forceinline__ void mma16816h(float* c, const uint32_t* a, const uint32_t* b) {
    asm volatile(
        "mma.sync.aligned.m16n8k16.row.col.f32.f16.f16.f32 "
        "{%0,%1,%2,%3}, {%4,%5,%6,%7}, {%8,%9}, {%0,%1,%2,%3};"
        : "+f"(c[0]), "+f"(c[1]), "+f"(c[2]), "+f"(c[3])
        : "r"(a[0]), "r"(a[1]), "r"(a[2]), "r"(a[3]), "r"(b[0]), "r"(b[1]));
}
__device__ __forceinline__ void cp16(uint32_t dst, const void* src) {
    asm volatile("cp.async.cg.shared.global [%0], [%1], 16;" :: "r"(dst), "l"(src));
}
#define CP_COMMIT() asm volatile("cp.async.commit_group;" ::: "memory")
#define CP_WAIT1()  asm volatile("cp.async.wait_group 1;" ::: "memory")
#define CP_WAIT0()  asm volatile("cp.async.wait_group 0;" ::: "memory")

// ---------------------------------------------------------------------------
// bf16 3-term path (qkv): CTA 128(M) x 256(N), K-chunk 64, 2-stage. (R13)
// ---------------------------------------------------------------------------
constexpr int OFF_AH = 0;
constexpr int OFF_AL = 16384;
constexpr int OFF_BH = 32768;
constexpr int OFF_BL = 65536;
constexpr int STAGE_BYTES = 98304;
constexpr int SMEM_BYTES  = 2 * STAGE_BYTES;  // 192 KB

__device__ __forceinline__ void load_stage(uint32_t st,
    const __nv_bfloat16* aH, const __nv_bfloat16* aL, int strideA,
    const __nv_bfloat16* bH, const __nv_bfloat16* bL, int strideB,
    int k0, int tid)
{
    #pragma unroll
    for (int i = 0; i < 4; i++) {
        int idx = tid + i * 256;
        int r   = idx >> 3;
        int c8  = (idx & 7) << 3;
        uint32_t sw = SWZ((uint32_t)(r * 128 + c8 * 2));
        size_t ga = (size_t)r * strideA + k0 + c8;
        cp16(st + OFF_AH + sw, aH + ga);
        cp16(st + OFF_AL + sw, aL + ga);
    }
    #pragma unroll
    for (int i = 0; i < 8; i++) {
        int idx = tid + i * 256;
        int r   = idx >> 3;
        int c8  = (idx & 7) << 3;
        uint32_t sw = SWZ((uint32_t)(r * 128 + c8 * 2));
        size_t gb = (size_t)r * strideB + k0 + c8;
        cp16(st + OFF_BH + sw, bH + gb);
        cp16(st + OFF_BL + sw, bL + gb);
    }
}

__device__ __forceinline__ void mma_consume(uint32_t st, float acc[4][8][4]) {
    const int lane = threadIdx.x & 31;
    const int wid  = threadIdx.x >> 5;
    const int wm   = (wid & 1) * 64;
    const int wn   = (wid >> 1) * 64;

    #pragma unroll
    for (int k16 = 0; k16 < 4; k16++) {
        uint32_t aH[4][4], aL[4][4], B[4][4];
        #pragma unroll
        for (int tm = 0; tm < 4; tm++) {
            int r  = wm + tm * 16 + (lane & 15);
            int ku = k16 * 2 + (lane >> 4);
            uint32_t off = SWZ((uint32_t)(r * 128 + ku * 16));
            ldsm_x4(aH[tm], st + OFF_AH + off);
            ldsm_x4(aL[tm], st + OFF_AL + off);
        }
        #pragma unroll
        for (int tb = 0; tb < 4; tb++) {
            int g  = lane >> 3;
            int r  = wn + tb * 16 + (g >> 1) * 8 + (lane & 7);
            int ku = k16 * 2 + (g & 1);
            ldsm_x4(B[tb], st + OFF_BH + SWZ((uint32_t)(r * 128 + ku * 16)));
        }
        #pragma unroll
        for (int tm = 0; tm < 4; tm++)
            #pragma unroll
            for (int tn = 0; tn < 8; tn++) {
                uint32_t bf[2];
                bf[0] = B[tn >> 1][(tn & 1) ? 2 : 0];
                bf[1] = B[tn >> 1][(tn & 1) ? 3 : 1];
                mma16816(acc[tm][tn], aH[tm], bf);
                mma16816(acc[tm][tn], aL[tm], bf);
            }
        #pragma unroll
        for (int tb = 0; tb < 4; tb++) {
            int g  = lane >> 3;
            int r  = wn + tb * 16 + (g >> 1) * 8 + (lane & 7);
            int ku = k16 * 2 + (g & 1);
            ldsm_x4(B[tb], st + OFF_BL + SWZ((uint32_t)(r * 128 + ku * 16)));
        }
        #pragma unroll
        for (int tm = 0; tm < 4; tm++)
            #pragma unroll
            for (int tn = 0; tn < 8; tn++) {
                uint32_t bf[2];
                bf[0] = B[tn >> 1][(tn & 1) ? 2 : 0];
                bf[1] = B[tn >> 1][(tn & 1) ? 3 : 1];
                mma16816(acc[tm][tn], aH[tm], bf);
            }
    }
}

__device__ __forceinline__ void gemm_pipeline(uint32_t sb, float acc[4][8][4],
    const __nv_bfloat16* aH, const __nv_bfloat16* aL, int strideA,
    const __nv_bfloat16* bH, const __nv_bfloat16* bL, int strideB,
    int NC, int tid)
{
    load_stage(sb, aH, aL, strideA, bH, bL, strideB, 0, tid);
    CP_COMMIT();
    for (int ch = 0; ch < NC; ++ch) {
        uint32_t cur = sb + (uint32_t)(ch & 1) * STAGE_BYTES;
        if (ch + 1 < NC) {
            uint32_t nxt = sb + (uint32_t)((ch + 1) & 1) * STAGE_BYTES;
            load_stage(nxt, aH, aL, strideA, bH, bL, strideB, (ch + 1) * 64, tid);
            CP_COMMIT();
            CP_WAIT1();
        } else {
            CP_WAIT0();
        }
        __syncthreads();
        mma_consume(cur, acc);
        __syncthreads();
    }
}

// ---------------------------------------------------------------------------
// Scores path: CTA 128(M=n) x 128(N=m), K-chunk 32, SW64 rows, 2-stage,
// 64 KB smem/CTA -> 2 CTAs/SM (launch_bounds(256,2), <=128 regs).
// 8 warps as 2(M) x 4(N); warp tile 64x32. acc[tm 0..3][tn 0..3][4].
// ---------------------------------------------------------------------------
constexpr int S2_AH = 0;
constexpr int S2_AL = 8192;
constexpr int S2_BH = 16384;
constexpr int S2_BL = 24576;
constexpr int S2_STAGE = 32768;
constexpr int S2_SMEM  = 2 * S2_STAGE;   // 64 KB

__device__ __forceinline__ void load_stage_s2(uint32_t st,
    const __nv_bfloat16* aH, const __nv_bfloat16* aL,
    const __nv_bfloat16* bH, const __nv_bfloat16* bL,
    int k0, int tid)
{
    // A and B tiles: 128 rows x 32 bf16 (64B rows), 512 uint4 each.
    #pragma unroll
    for (int i = 0; i < 2; i++) {
        int idx = tid + i * 256;
        int r   = idx >> 2;
        int u   = idx & 3;
        uint32_t sw = SWZ64((uint32_t)(r * 64 + u * 16));
        size_t g = (size_t)r * DIM + k0 + u * 8;
        cp16(st + S2_AH + sw, aH + g);
        cp16(st + S2_AL + sw, aL + g);
        cp16(st + S2_BH + sw, bH + g);
        cp16(st + S2_BL + sw, bL + g);
    }
}

__device__ __forceinline__ void mma_consume_s2(uint32_t st, float acc[4][4][4]) {
    const int lane = threadIdx.x & 31;
    const int wid  = threadIdx.x >> 5;
    const int wm   = (wid & 1) * 64;
    const int wn   = (wid >> 1) * 32;

    #pragma unroll
    for (int k16 = 0; k16 < 2; k16++) {
        uint32_t aH[4][4], aL[4][4], BH[2][4], BL[2][4];
        #pragma unroll
        for (int tm = 0; tm < 4; tm++) {
            int r  = wm + tm * 16 + (lane & 15);
            int ku = k16 * 2 + (lane >> 4);
            uint32_t off = SWZ64((uint32_t)(r * 64 + ku * 16));
            ldsm_x4(aH[tm], st + S2_AH + off);
            ldsm_x4(aL[tm], st + S2_AL + off);
        }
        #pragma unroll
        for (int tb = 0; tb < 2; tb++) {
            int g  = lane >> 3;
            int r  = wn + tb * 16 + (g >> 1) * 8 + (lane & 7);
            int ku = k16 * 2 + (g & 1);
            uint32_t off = SWZ64((uint32_t)(r * 64 + ku * 16));
            ldsm_x4(BH[tb], st + S2_BH + off);
            ldsm_x4(BL[tb], st + S2_BL + off);
        }
        #pragma unroll
        for (int tm = 0; tm < 4; tm++)
            #pragma unroll
            for (int tn = 0; tn < 4; tn++) {
                uint32_t bfH[2], bfL[2];
                bfH[0] = BH[tn >> 1][(tn & 1) ? 2 : 0];
                bfH[1] = BH[tn >> 1][(tn & 1) ? 3 : 1];
                bfL[0] = BL[tn >> 1][(tn & 1) ? 2 : 0];
                bfL[1] = BL[tn >> 1][(tn & 1) ? 3 : 1];
                mma16816(acc[tm][tn], aH[tm], bfH);
                mma16816(acc[tm][tn], aL[tm], bfH);
                mma16816(acc[tm][tn], aH[tm], bfL);
            }
    }
}

// ---------------------------------------------------------------------------
// fp16 2-term PV path (R13): A single (vt fp16), B pair (P hi/lo fp16).
// ---------------------------------------------------------------------------
constexpr int OFF_PA  = 0;
constexpr int OFF_PBH = 16384;
constexpr int OFF_PBL = 49152;
constexpr int PV_STAGE_BYTES = 81920;
constexpr int PV_SMEM_BYTES  = 2 * PV_STAGE_BYTES;  // 160 KB

__device__ __forceinline__ void load_stage_pv(uint32_t st,
    const __half* a, int strideA,
    const __half* bH, const __half* bL, int strideB,
    int k0, int tid)
{
    #pragma unroll
    for (int i = 0; i < 4; i++) {
        int idx = tid + i * 256;
        int r   = idx >> 3;
        int c8  = (idx & 7) << 3;
        uint32_t sw = SWZ((uint32_t)(r * 128 + c8 * 2));
        cp16(st + OFF_PA + sw, a + (size_t)r * strideA + k0 + c8);
    }
    #pragma unroll
    for (int i = 0; i < 8; i++) {
        int idx = tid + i * 256;
        int r   = idx >> 3;
        int c8  = (idx & 7) << 3;
        uint32_t sw = SWZ((uint32_t)(r * 128 + c8 * 2));
        size_t gb = (size_t)r * strideB + k0 + c8;
        cp16(st + OFF_PBH + sw, bH + gb);
        cp16(st + OFF_PBL + sw, bL + gb);
    }
}

__device__ __forceinline__ void mma_consume_pv(uint32_t st, float acc[4][8][4]) {
    const int lane = threadIdx.x & 31;
    const int wid  = threadIdx.x >> 5;
    const int wm   = (wid & 1) * 64;
    const int wn   = (wid >> 1) * 64;

    #pragma unroll
    for (int k16 = 0; k16 < 4; k16++) {
        uint32_t A[4][4], B[4][4];
        #pragma unroll
        for (int tm = 0; tm < 4; tm++) {
            int r  = wm + tm * 16 + (lane & 15);
            int ku = k16 * 2 + (lane >> 4);
            ldsm_x4(A[tm], st + OFF_PA + SWZ((uint32_t)(r * 128 + ku * 16)));
        }
        #pragma unroll
        for (int tb = 0; tb < 4; tb++) {
            int g  = lane >> 3;
            int r  = wn + tb * 16 + (g >> 1) * 8 + (lane & 7);
            int ku = k16 * 2 + (g & 1);
            ldsm_x4(B[tb], st + OFF_PBH + SWZ((uint32_t)(r * 128 + ku * 16)));
        }
        #pragma unroll
        for (int tm = 0; tm < 4; tm++)
            #pragma unroll
            for (int tn = 0; tn < 8; tn++) {
                uint32_t bf[2];
                bf[0] = B[tn >> 1][(tn & 1) ? 2 : 0];
                bf[1] = B[tn >> 1][(tn & 1) ? 3 : 1];
                mma16816h(acc[tm][tn], A[tm], bf);
            }
        #pragma unroll
        for (int tb = 0; tb < 4; tb++) {
            int g  = lane >> 3;
            int r  = wn + tb * 16 + (g >> 1) * 8 + (lane & 7);
            int ku = k16 * 2 + (g & 1);
            ldsm_x4(B[tb], st + OFF_PBL + SWZ((uint32_t)(r * 128 + ku * 16)));
        }
        #pragma unroll
        for (int tm = 0; tm < 4; tm++)
            #pragma unroll
            for (int tn = 0; tn < 8; tn++) {
                uint32_t bf[2];
                bf[0] = B[tn >> 1][(tn & 1) ? 2 : 0];
                bf[1] = B[tn >> 1][(tn & 1) ? 3 : 1];
                mma16816h(acc[tm][tn], A[tm], bf);
            }
    }
}

__device__ __forceinline__ void pv_pipeline(uint32_t sb, float acc[4][8][4],
    const __half* a, int strideA,
    const __half* bH, const __half* bL, int strideB,
    int NC, int tid)
{
    load_stage_pv(sb, a, strideA, bH, bL, strideB, 0, tid);
    CP_COMMIT();
    for (int ch = 0; ch < NC; ++ch) {
        uint32_t cur = sb + (uint32_t)(ch & 1) * PV_STAGE_BYTES;
        if (ch + 1 < NC) {
            uint32_t nxt = sb + (uint32_t)((ch + 1) & 1) * PV_STAGE_BYTES;
            load_stage_pv(nxt, a, strideA, bH, bL, strideB, (ch + 1) * 64, tid);
            CP_COMMIT();
            CP_WAIT1();
        } else {
            CP_WAIT0();
        }
        __syncthreads();
        mma_consume_pv(cur, acc);
        __syncthreads();
    }
}

// ---------------------------------------------------------------------------
// Prep 1: split W into bf16 hi/lo.
// ---------------------------------------------------------------------------
__global__ __launch_bounds__(256) void prep_w_kernel(
    const float* __restrict__ Wq, const float* __restrict__ Wk, const float* __restrict__ Wv)
{
    const int which = blockIdx.y;
    const float* W = (which == 0) ? Wq : (which == 1) ? Wk : Wv;
    int idx = blockIdx.x * 256 + threadIdx.x;
    float4 v = *(const float4*)(W + (size_t)idx * 4);
    __nv_bfloat16 h0,h1,h2,h3,l0,l1,l2,l3;
    split2(v.x, h0, l0); split2(v.y, h1, l1);
    split2(v.z, h2, l2); split2(v.w, h3, l3);
    *(uint2*)(&g_w_hi[which][(size_t)idx * 4]) = make_uint2(pack2(h0,h1), pack2(h2,h3));
    *(uint2*)(&g_w_lo[which][(size_t)idx * 4]) = make_uint2(pack2(l0,l1), pack2(l2,l3));
}

// ---------------------------------------------------------------------------
// Prep 2: transpose + split x[b][c][n] -> xt[b][n][c] hi/lo.
// ---------------------------------------------------------------------------
__global__ __launch_bounds__(256) void prep_x_kernel(const float* __restrict__ x)
{
    __shared__ float tile[32][33];
    const int n0 = blockIdx.x * 32;
    const int c0 = blockIdx.y * 32;
    const int b  = blockIdx.z;
    const int tid = threadIdx.x;

    {
        int c  = tid >> 3;
        int n4 = (tid & 7) << 2;
        float4 v = *(const float4*)(x + ((size_t)b * DIM + c0 + c) * SEQ + n0 + n4);
        tile[c][n4 + 0] = v.x; tile[c][n4 + 1] = v.y;
        tile[c][n4 + 2] = v.z; tile[c][n4 + 3] = v.w;
    }
    __syncthreads();
    {
        int n  = tid >> 3;
        int c4 = (tid & 7) << 2;
        float f0 = tile[c4 + 0][n], f1 = tile[c4 + 1][n];
        float f2 = tile[c4 + 2][n], f3 = tile[c4 + 3][n];
        __nv_bfloat16 h0,h1,h2,h3,l0,l1,l2,l3;
        split2(f0, h0, l0); split2(f1, h1, l1);
        split2(f2, h2, l2); split2(f3, h3, l3);
        size_t off = ((size_t)b * SEQ + n0 + n) * DIM + c0 + c4;
        *(uint2*)(g_xt_hi + off) = make_uint2(pack2(h0,h1), pack2(h2,h3));
        *(uint2*)(g_xt_lo + off) = make_uint2(pack2(l0,l1), pack2(l2,l3));
    }
}

// ---------------------------------------------------------------------------
// Kernel 1: QKV projection (bf16 3-term, R13 unchanged).
// ---------------------------------------------------------------------------
constexpr int VSTRIDE = 136;

__global__ __launch_bounds__(256) void qkv_kernel(
    const float* __restrict__ bq, const float* __restrict__ bk, const float* __restrict__ bv)
{
    extern __shared__ char smem[];
    const uint32_t sb = smem_to_u32(smem);
    const int tid = threadIdx.x;
    const int z = blockIdx.z, which = z >> 3, b = z & 7;
    const float* bias = (which == 0) ? bq : (which == 1) ? bk : bv;

    const int n0 = blockIdx.x * 128;
    const int d0 = blockIdx.y * 256;

    const __nv_bfloat16* aH = g_xt_hi + ((size_t)b * SEQ + n0) * DIM;
    const __nv_bfloat16* aL = g_xt_lo + ((size_t)b * SEQ + n0) * DIM;
    const __nv_bfloat16* bH = &g_w_hi[which][(size_t)d0 * DIM];
    const __nv_bfloat16* bL = &g_w_lo[which][(size_t)d0 * DIM];

    float acc[4][8][4] = {};
    gemm_pipeline(sb, acc, aH, aL, DIM, bH, bL, DIM, DIM / 64, tid);

    const int lane = tid & 31, wid = tid >> 5;
    const int g = lane >> 2, t = lane & 3;
    const int wm = (wid & 1) * 64, wn = (wid >> 1) * 64;

    if (which < 2) {
        __nv_bfloat16* out_hi = (which == 0) ? g_q_hi : g_k_hi;
        __nv_bfloat16* out_lo = (which == 0) ? g_q_lo : g_k_lo;
        #pragma unroll
        for (int tn = 0; tn < 8; tn++) {
            const int d = d0 + wn + tn * 8 + t * 2;
            const float b0 = bias[d], b1 = bias[d + 1];
            #pragma unroll
            for (int tm = 0; tm < 4; tm++)
                #pragma unroll
                for (int h = 0; h < 2; h++) {
                    int n = n0 + wm + tm * 16 + g + h * 8;
                    float f0 = acc[tm][tn][2 * h + 0] + b0;
                    float f1 = acc[tm][tn][2 * h + 1] + b1;
                    __nv_bfloat16 h0, l0, h1, l1;
                    split2(f0, h0, l0); split2(f1, h1, l1);
                    size_t off = ((size_t)b * SEQ + n) * DIM + d;
                    *(uint32_t*)(out_hi + off) = pack2(h0, h1);
                    *(uint32_t*)(out_lo + off) = pack2(l0, l1);
                }
        }
    } else {
        float* stage = (float*)smem;
        #pragma unroll
        for (int tn = 0; tn < 8; tn++) {
            const int dl = wn + tn * 8 + t * 2;
            const float b0 = bias[d0 + dl], b1 = bias[d0 + dl + 1];
            #pragma unroll
            for (int tm = 0; tm < 4; tm++)
                #pragma unroll
                for (int h = 0; h < 2; h++) {
                    int nl = wm + tm * 16 + g + h * 8;
                    stage[(size_t)dl * VSTRIDE + nl]       = acc[tm][tn][2 * h + 0] + b0;
                    stage[(size_t)(dl + 1) * VSTRIDE + nl] = acc[tm][tn][2 * h + 1] + b1;
                }
        }
        __syncthreads();
        #pragma unroll
        for (int i = 0; i < 8; i++) {
            int row = i * 32 + (tid >> 3);
            int col = (tid & 7) * 16;
            const float* src = stage + (size_t)row * VSTRIDE + col;
            __half eh[16];
            #pragma unroll
            for (int j = 0; j < 16; j += 4) {
                float4 v = *(const float4*)(src + j);
                eh[j+0] = __float2half(v.x); eh[j+1] = __float2half(v.y);
                eh[j+2] = __float2half(v.z); eh[j+3] = __float2half(v.w);
            }
            size_t off = ((size_t)b * DIM + d0 + row) * SEQ + n0 + col;
            *(uint4*)(g_vt + off)     = *(uint4*)(eh);
            *(uint4*)(g_vt + off + 8) = *(uint4*)(eh + 8);
        }
    }
}

// ---------------------------------------------------------------------------
// Kernel 2: scores (bf16 3-term, 128x128 tile, 2 CTAs/SM).
// grid (SEQ/128 m, SEQ/128 n, BATCH), block 256
// ---------------------------------------------------------------------------
__global__ __launch_bounds__(256, 2) void scores_kernel()
{
    extern __shared__ char smem[];
    const uint32_t sb = smem_to_u32(smem);
    const int tid = threadIdx.x;
    const int b  = blockIdx.z;
    const int m0 = blockIdx.x * 128;
    const int n0 = blockIdx.y * 128;

    const __nv_bfloat16* aH = g_q_hi + ((size_t)b * SEQ + n0) * DIM;
    const __nv_bfloat16* aL = g_q_lo + ((size_t)b * SEQ + n0) * DIM;
    const __nv_bfloat16* bH = g_k_hi + ((size_t)b * SEQ + m0) * DIM;
    const __nv_bfloat16* bL = g_k_lo + ((size_t)b * SEQ + m0) * DIM;

    float acc[4][4][4] = {};

    // 2-stage ring, K-chunk 32, NC = 16
    load_stage_s2(sb, aH, aL, bH, bL, 0, tid);
    CP_COMMIT();
    const int NC = DIM / 32;
    for (int ch = 0; ch < NC; ++ch) {
        uint32_t cur = sb + (uint32_t)(ch & 1) * S2_STAGE;
        if (ch + 1 < NC) {
            uint32_t nxt = sb + (uint32_t)((ch + 1) & 1) * S2_STAGE;
            load_stage_s2(nxt, aH, aL, bH, bL, (ch + 1) * 32, tid);
            CP_COMMIT();
            CP_WAIT1();
        } else {
            CP_WAIT0();
        }
        __syncthreads();
        mma_consume_s2(cur, acc);
        __syncthreads();
    }

    const int lane = tid & 31, wid = tid >> 5;
    const int g = lane >> 2, t = lane & 3;
    const int wm = (wid & 1) * 64, wn = (wid >> 1) * 32;
    float* S = g_scores + (size_t)b * SEQ * SEQ;
    #pragma unroll
    for (int tm = 0; tm < 4; tm++)
        #pragma unroll
        for (int h = 0; h < 2; h++) {
            int n = n0 + wm + tm * 16 + g + h * 8;
            #pragma unroll
            for (int tn = 0; tn < 4; tn++) {
                int m = m0 + wn + tn * 8 + t * 2;
                float2 v = make_float2(acc[tm][tn][2 * h], acc[tm][tn][2 * h + 1]);
                *(float2*)(S + (size_t)n * SEQ + m) = v;
            }
        }
}

// ---------------------------------------------------------------------------
// Kernel 3: row softmax (vectorized); fp32 scores in, split fp16 P out.
// ---------------------------------------------------------------------------
__global__ __launch_bounds__(256) void softmax_kernel()
{
    const int row = blockIdx.x;
    const float* p = g_scores + (size_t)row * SEQ;
    const int t = threadIdx.x;

    float v[8];
    {
        float4 a = *(const float4*)(p + t * 4);
        float4 b = *(const float4*)(p + 1024 + t * 4);
        v[0]=a.x; v[1]=a.y; v[2]=a.z; v[3]=a.w;
        v[4]=b.x; v[5]=b.y; v[6]=b.z; v[7]=b.w;
    }
    float mx = v[0];
    #pragma unroll
    for (int i = 1; i < 8; i++) mx = fmaxf(mx, v[i]);

    __shared__ float red[8];
    #pragma unroll
    for (int o = 16; o > 0; o >>= 1) mx = fmaxf(mx, __shfl_xor_sync(0xffffffffu, mx, o));
    if ((t & 31) == 0) red[t >> 5] = mx;
    __syncthreads();
    mx = red[0];
    #pragma unroll
    for (int w = 1; w < 8; w++) mx = fmaxf(mx, red[w]);
    __syncthreads();

    float s = 0.f;
    #pragma unroll
    for (int i = 0; i < 8; i++) { v[i] = __expf(v[i] - mx); s += v[i]; }
    #pragma unroll
    for (int o = 16; o > 0; o >>= 1) s += __shfl_xor_sync(0xffffffffu, s, o);
    if ((t & 31) == 0) red[t >> 5] = s;
    __syncthreads();
    s = red[0];
    #pragma unroll
    for (int w = 1; w < 8; w++) s += red[w];

    const float inv = 1.0f / s;
    __half h[8], l[8];
    #pragma unroll
    for (int i = 0; i < 8; i++) split2h(v[i] * inv, h[i], l[i]);

    size_t base = (size_t)row * SEQ;
    *(uint2*)(g_p_hi + base + t * 4)        = make_uint2(pack2h(h[0],h[1]), pack2h(h[2],h[3]));
    *(uint2*)(g_p_hi + base + 1024 + t * 4) = make_uint2(pack2h(h[4],h[5]), pack2h(h[6],h[7]));
    *(uint2*)(g_p_lo + base + t * 4)        = make_uint2(pack2h(l[0],l[1]), pack2h(l[2],l[3]));
    *(uint2*)(g_p_lo + base + 1024 + t * 4) = make_uint2(pack2h(l[4],l[5]), pack2h(l[6],l[7]));
}

// ---------------------------------------------------------------------------
// Kernel 4: out[b][d][n] = sum_m vt[d][m] * (pH + pL)[n][m]   (fp16 2-term)
// grid (SEQ/256 n, DIM/128 d, BATCH), block 256
// ---------------------------------------------------------------------------
__global__ __launch_bounds__(256) void pv_kernel(float* __restrict__ out)
{
    extern __shared__ char smem[];
    const uint32_t sb = smem_to_u32(smem);
    const int tid = threadIdx.x;
    const int b  = blockIdx.z;
    const int n0 = blockIdx.x * 256;
    const int d0 = blockIdx.y * 128;

    const __half* a  = g_vt   + ((size_t)b * DIM + d0) * SEQ;
    const __half* bH = g_p_hi + ((size_t)b * SEQ + n0) * SEQ;
    const __half* bL = g_p_lo + ((size_t)b * SEQ + n0) * SEQ;

    float acc[4][8][4] = {};
    pv_pipeline(sb, acc, a, SEQ, bH, bL, SEQ, SEQ / 64, tid);

    const int lane = tid & 31, wid = tid >> 5;
    const int g = lane >> 2, t = lane & 3;
    const int wm = (wid & 1) * 64, wn = (wid >> 1) * 64;
    float* ob = out + (size_t)b * DIM * SEQ;
    #pragma unroll
    for (int tm = 0; tm < 4; tm++)
        #pragma unroll
        for (int h = 0; h < 2; h++) {
            int d = d0 + wm + tm * 16 + g + h * 8;
            #pragma unroll
            for (int tn = 0; tn < 8; tn++) {
                int n = n0 + wn + tn * 8 + t * 2;
                float2 v = make_float2(acc[tm][tn][2 * h], acc[tm][tn][2 * h + 1]);
                *(float2*)(ob + (size_t)d * SEQ + n) = v;
            }
        }
}

// ---------------------------------------------------------------------------
extern "C" void kernel_launch(void* const* d_in, const int* in_sizes, int n_in,
                              void* d_out, int out_size)
{
    (void)in_sizes; (void)n_in; (void)out_size;
    const float* x  = (const float*)d_in[0];
    const float* Wq = (const float*)d_in[1];
    const float* bq = (const float*)d_in[2];
    const float* Wk = (const float*)d_in[3];
    const float* bk = (const float*)d_in[4];
    const float* Wv = (const float*)d_in[5];
    const float* bv = (const float*)d_in[6];
    float* out = (float*)d_out;

    cudaFuncSetAttribute(qkv_kernel,    cudaFuncAttributeMaxDynamicSharedMemorySize, SMEM_BYTES);
    cudaFuncSetAttribute(scores_kernel, cudaFuncAttributeMaxDynamicSharedMemorySize, S2_SMEM);
    cudaFuncSetAttribute(pv_kernel,     cudaFuncAttributeMaxDynamicSharedMemorySize, PV_SMEM_BYTES);

    prep_w_kernel<<<dim3(256, 3), 256>>>(Wq, Wk, Wv);
    prep_x_kernel<<<dim3(SEQ / 32, DIM / 32, BATCH), 256>>>(x);
    qkv_kernel<<<dim3(SEQ / 128, DIM / 256, 3 * BATCH), 256, SMEM_BYTES>>>(bq, bk, bv);
    scores_kernel<<<dim3(SEQ / 128, SEQ / 128, BATCH), 256, S2_SMEM>>>();
    softmax_kernel<<<BATCH * SEQ, 256>>>();
    pv_kernel<<<dim3(SEQ / 256, DIM / 128, BATCH), 256, PV_SMEM_BYTES>>>(out);
}

// round 16
// speedup vs baseline: 1.4939x; 1.4939x over previous
#include <cuda_runtime.h>
#include <cuda_bf16.h>
#include <cuda_fp16.h>
#include <cstdint>
#include <math_constants.h>

constexpr int BATCH = 8;
constexpr int DIM   = 512;
constexpr int SEQ   = 2048;

// ---------------------------------------------------------------------------
// Scratch (device globals; no allocation allowed)
// ---------------------------------------------------------------------------
__device__ __align__(128) __nv_bfloat16 g_xt_hi[(size_t)BATCH * SEQ * DIM]; // [b][n][c]
__device__ __align__(128) __nv_bfloat16 g_xt_lo[(size_t)BATCH * SEQ * DIM];
__device__ __align__(128) __nv_bfloat16 g_w_hi[3][(size_t)DIM * DIM];      // [which][d][c]
__device__ __align__(128) __nv_bfloat16 g_w_lo[3][(size_t)DIM * DIM];
__device__ __align__(128) __nv_bfloat16 g_q_hi[(size_t)BATCH * SEQ * DIM]; // [b][n][d]
__device__ __align__(128) __nv_bfloat16 g_q_lo[(size_t)BATCH * SEQ * DIM];
__device__ __align__(128) __nv_bfloat16 g_k_hi[(size_t)BATCH * SEQ * DIM];
__device__ __align__(128) __nv_bfloat16 g_k_lo[(size_t)BATCH * SEQ * DIM];
__device__ __align__(128) __half        g_vt   [(size_t)BATCH * DIM * SEQ]; // [b][d][m] fp16
__device__ __align__(128) float         g_scores[(size_t)BATCH * SEQ * SEQ];
__device__ __align__(128) __half        g_p_hi[(size_t)BATCH * SEQ * SEQ]; // [b][n][m] fp16
__device__ __align__(128) __half        g_p_lo[(size_t)BATCH * SEQ * SEQ];

// ---------------------------------------------------------------------------
// Helpers
// ---------------------------------------------------------------------------
__device__ __forceinline__ uint32_t smem_to_u32(const void* p) {
    uint32_t a;
    asm("{ .reg .u64 t; cvta.to.shared.u64 t, %1; cvt.u32.u64 %0, t; }" : "=r"(a) : "l"(p));
    return a;
}
#define SWZ(x) ((x) ^ (((x) >> 3) & 0x70))

__device__ __forceinline__ void split2(float f, __nv_bfloat16& h, __nv_bfloat16& l) {
    h = __float2bfloat16(f);
    l = __float2bfloat16(f - __bfloat162float(h));
}
__device__ __forceinline__ uint32_t pack2(__nv_bfloat16 a, __nv_bfloat16 b) {
    __nv_bfloat162 t = __halves2bfloat162(a, b);
    return *reinterpret_cast<uint32_t*>(&t);
}
__device__ __forceinline__ void split2h(float f, __half& h, __half& l) {
    h = __float2half(f);
    l = __float2half(f - __half2float(h));
}
__device__ __forceinline__ uint32_t pack2h(__half a, __half b) {
    __half2 t = __halves2half2(a, b);
    return *reinterpret_cast<uint32_t*>(&t);
}

__device__ __forceinline__ void ldsm_x4(uint32_t* r, uint32_t addr) {
    asm volatile("ldmatrix.sync.aligned.m8n8.x4.shared.b16 {%0,%1,%2,%3}, [%4];"
        : "=r"(r[0]), "=r"(r[1]), "=r"(r[2]), "=r"(r[3]) : "r"(addr));
}
__device__ __forceinline__ void mma16816(float* c, const uint32_t* a, const uint32_t* b) {
    asm volatile(
        "mma.sync.aligned.m16n8k16.row.col.f32.bf16.bf16.f32 "
        "{%0,%1,%2,%3}, {%4,%5,%6,%7}, {%8,%9}, {%0,%1,%2,%3};"
        : "+f"(c[0]), "+f"(c[1]), "+f"(c[2]), "+f"(c[3])
        : "r"(a[0]), "r"(a[1]), "r"(a[2]), "r"(a[3]), "r"(b[0]), "r"(b[1]));
}
__device__ __forceinline__ void mma16816h(float* c, const uint32_t* a, const uint32_t* b) {
    asm volatile(
        "mma.sync.aligned.m16n8k16.row.col.f32.f16.f16.f32 "
        "{%0,%1,%2,%3}, {%4,%5,%6,%7}, {%8,%9}, {%0,%1,%2,%3};"
        : "+f"(c[0]), "+f"(c[1]), "+f"(c[2]), "+f"(c[3])
        : "r"(a[0]), "r"(a[1]), "r"(a[2]), "r"(a[3]), "r"(b[0]), "r"(b[1]));
}
__device__ __forceinline__ void cp16(uint32_t dst, const void* src) {
    asm volatile("cp.async.cg.shared.global [%0], [%1], 16;" :: "r"(dst), "l"(src));
}
#define CP_COMMIT() asm volatile("cp.async.commit_group;" ::: "memory")
#define CP_WAIT1()  asm volatile("cp.async.wait_group 1;" ::: "memory")
#define CP_WAIT0()  asm volatile("cp.async.wait_group 0;" ::: "memory")

// ---------------------------------------------------------------------------
// bf16 3-term path (qkv, scores): CTA 128(M) x 256(N), K-chunk 64, 2-stage.
// ---------------------------------------------------------------------------
constexpr int OFF_AH = 0;
constexpr int OFF_AL = 16384;
constexpr int OFF_BH = 32768;
constexpr int OFF_BL = 65536;
constexpr int STAGE_BYTES = 98304;
constexpr int SMEM_BYTES  = 2 * STAGE_BYTES;  // 192 KB

__device__ __forceinline__ void load_stage(uint32_t st,
    const __nv_bfloat16* aH, const __nv_bfloat16* aL, int strideA,
    const __nv_bfloat16* bH, const __nv_bfloat16* bL, int strideB,
    int k0, int tid)
{
    #pragma unroll
    for (int i = 0; i < 4; i++) {
        int idx = tid + i * 256;
        int r   = idx >> 3;
        int c8  = (idx & 7) << 3;
        uint32_t sw = SWZ((uint32_t)(r * 128 + c8 * 2));
        size_t ga = (size_t)r * strideA + k0 + c8;
        cp16(st + OFF_AH + sw, aH + ga);
        cp16(st + OFF_AL + sw, aL + ga);
    }
    #pragma unroll
    for (int i = 0; i < 8; i++) {
        int idx = tid + i * 256;
        int r   = idx >> 3;
        int c8  = (idx & 7) << 3;
        uint32_t sw = SWZ((uint32_t)(r * 128 + c8 * 2));
        size_t gb = (size_t)r * strideB + k0 + c8;
        cp16(st + OFF_BH + sw, bH + gb);
        cp16(st + OFF_BL + sw, bL + gb);
    }
}

// acc += AH*BH + AL*BH + AH*BL  (R7-proven ordering)
__device__ __forceinline__ void mma_consume(uint32_t st, float acc[4][8][4]) {
    const int lane = threadIdx.x & 31;
    const int wid  = threadIdx.x >> 5;
    const int wm   = (wid & 1) * 64;
    const int wn   = (wid >> 1) * 64;

    #pragma unroll
    for (int k16 = 0; k16 < 4; k16++) {
        uint32_t aH[4][4], aL[4][4], B[4][4];
        #pragma unroll
        for (int tm = 0; tm < 4; tm++) {
            int r  = wm + tm * 16 + (lane & 15);
            int ku = k16 * 2 + (lane >> 4);
            uint32_t off = SWZ((uint32_t)(r * 128 + ku * 16));
            ldsm_x4(aH[tm], st + OFF_AH + off);
            ldsm_x4(aL[tm], st + OFF_AL + off);
        }
        #pragma unroll
        for (int tb = 0; tb < 4; tb++) {
            int g  = lane >> 3;
            int r  = wn + tb * 16 + (g >> 1) * 8 + (lane & 7);
            int ku = k16 * 2 + (g & 1);
            ldsm_x4(B[tb], st + OFF_BH + SWZ((uint32_t)(r * 128 + ku * 16)));
        }
        #pragma unroll
        for (int tm = 0; tm < 4; tm++)
            #pragma unroll
            for (int tn = 0; tn < 8; tn++) {
                uint32_t bf[2];
                bf[0] = B[tn >> 1][(tn & 1) ? 2 : 0];
                bf[1] = B[tn >> 1][(tn & 1) ? 3 : 1];
                mma16816(acc[tm][tn], aH[tm], bf);
                mma16816(acc[tm][tn], aL[tm], bf);
            }
        #pragma unroll
        for (int tb = 0; tb < 4; tb++) {
            int g  = lane >> 3;
            int r  = wn + tb * 16 + (g >> 1) * 8 + (lane & 7);
            int ku = k16 * 2 + (g & 1);
            ldsm_x4(B[tb], st + OFF_BL + SWZ((uint32_t)(r * 128 + ku * 16)));
        }
        #pragma unroll
        for (int tm = 0; tm < 4; tm++)
            #pragma unroll
            for (int tn = 0; tn < 8; tn++) {
                uint32_t bf[2];
                bf[0] = B[tn >> 1][(tn & 1) ? 2 : 0];
                bf[1] = B[tn >> 1][(tn & 1) ? 3 : 1];
                mma16816(acc[tm][tn], aH[tm], bf);
            }
    }
}

__device__ __forceinline__ void gemm_pipeline(uint32_t sb, float acc[4][8][4],
    const __nv_bfloat16* aH, const __nv_bfloat16* aL, int strideA,
    const __nv_bfloat16* bH, const __nv_bfloat16* bL, int strideB,
    int NC, int tid)
{
    load_stage(sb, aH, aL, strideA, bH, bL, strideB, 0, tid);
    CP_COMMIT();
    for (int ch = 0; ch < NC; ++ch) {
        uint32_t cur = sb + (uint32_t)(ch & 1) * STAGE_BYTES;
        if (ch + 1 < NC) {
            uint32_t nxt = sb + (uint32_t)((ch + 1) & 1) * STAGE_BYTES;
            load_stage(nxt, aH, aL, strideA, bH, bL, strideB, (ch + 1) * 64, tid);
            CP_COMMIT();
            CP_WAIT1();
        } else {
            CP_WAIT0();
        }
        __syncthreads();
        mma_consume(cur, acc);
        __syncthreads();
    }
}

// ---------------------------------------------------------------------------
// fp16 2-term PV path: A single (vt fp16), B pair (P hi/lo fp16).
// Per-stage: A 16KB + BH 32KB + BL 32KB = 80KB; 2 stages = 160KB.
// ---------------------------------------------------------------------------
constexpr int OFF_PA  = 0;
constexpr int OFF_PBH = 16384;
constexpr int OFF_PBL = 49152;
constexpr int PV_STAGE_BYTES = 81920;
constexpr int PV_SMEM_BYTES  = 2 * PV_STAGE_BYTES;  // 160 KB

__device__ __forceinline__ void load_stage_pv(uint32_t st,
    const __half* a, int strideA,
    const __half* bH, const __half* bL, int strideB,
    int k0, int tid)
{
    #pragma unroll
    for (int i = 0; i < 4; i++) {
        int idx = tid + i * 256;
        int r   = idx >> 3;
        int c8  = (idx & 7) << 3;
        uint32_t sw = SWZ((uint32_t)(r * 128 + c8 * 2));
        cp16(st + OFF_PA + sw, a + (size_t)r * strideA + k0 + c8);
    }
    #pragma unroll
    for (int i = 0; i < 8; i++) {
        int idx = tid + i * 256;
        int r   = idx >> 3;
        int c8  = (idx & 7) << 3;
        uint32_t sw = SWZ((uint32_t)(r * 128 + c8 * 2));
        size_t gb = (size_t)r * strideB + k0 + c8;
        cp16(st + OFF_PBH + sw, bH + gb);
        cp16(st + OFF_PBL + sw, bL + gb);
    }
}

// acc += A*BH + A*BL   (fp16)
__device__ __forceinline__ void mma_consume_pv(uint32_t st, float acc[4][8][4]) {
    const int lane = threadIdx.x & 31;
    const int wid  = threadIdx.x >> 5;
    const int wm   = (wid & 1) * 64;
    const int wn   = (wid >> 1) * 64;

    #pragma unroll
    for (int k16 = 0; k16 < 4; k16++) {
        uint32_t A[4][4], B[4][4];
        #pragma unroll
        for (int tm = 0; tm < 4; tm++) {
            int r  = wm + tm * 16 + (lane & 15);
            int ku = k16 * 2 + (lane >> 4);
            ldsm_x4(A[tm], st + OFF_PA + SWZ((uint32_t)(r * 128 + ku * 16)));
        }
        #pragma unroll
        for (int tb = 0; tb < 4; tb++) {
            int g  = lane >> 3;
            int r  = wn + tb * 16 + (g >> 1) * 8 + (lane & 7);
            int ku = k16 * 2 + (g & 1);
            ldsm_x4(B[tb], st + OFF_PBH + SWZ((uint32_t)(r * 128 + ku * 16)));
        }
        #pragma unroll
        for (int tm = 0; tm < 4; tm++)
            #pragma unroll
            for (int tn = 0; tn < 8; tn++) {
                uint32_t bf[2];
                bf[0] = B[tn >> 1][(tn & 1) ? 2 : 0];
                bf[1] = B[tn >> 1][(tn & 1) ? 3 : 1];
                mma16816h(acc[tm][tn], A[tm], bf);
            }
        #pragma unroll
        for (int tb = 0; tb < 4; tb++) {
            int g  = lane >> 3;
            int r  = wn + tb * 16 + (g >> 1) * 8 + (lane & 7);
            int ku = k16 * 2 + (g & 1);
            ldsm_x4(B[tb], st + OFF_PBL + SWZ((uint32_t)(r * 128 + ku * 16)));
        }
        #pragma unroll
        for (int tm = 0; tm < 4; tm++)
            #pragma unroll
            for (int tn = 0; tn < 8; tn++) {
                uint32_t bf[2];
                bf[0] = B[tn >> 1][(tn & 1) ? 2 : 0];
                bf[1] = B[tn >> 1][(tn & 1) ? 3 : 1];
                mma16816h(acc[tm][tn], A[tm], bf);
            }
    }
}

__device__ __forceinline__ void pv_pipeline(uint32_t sb, float acc[4][8][4],
    const __half* a, int strideA,
    const __half* bH, const __half* bL, int strideB,
    int NC, int tid)
{
    load_stage_pv(sb, a, strideA, bH, bL, strideB, 0, tid);
    CP_COMMIT();
    for (int ch = 0; ch < NC; ++ch) {
        uint32_t cur = sb + (uint32_t)(ch & 1) * PV_STAGE_BYTES;
        if (ch + 1 < NC) {
            uint32_t nxt = sb + (uint32_t)((ch + 1) & 1) * PV_STAGE_BYTES;
            load_stage_pv(nxt, a, strideA, bH, bL, strideB, (ch + 1) * 64, tid);
            CP_COMMIT();
            CP_WAIT1();
        } else {
            CP_WAIT0();
        }
        __syncthreads();
        mma_consume_pv(cur, acc);
        __syncthreads();
    }
}

// ---------------------------------------------------------------------------
// Prep 1: split W into bf16 hi/lo.  grid (256, 3), block 256.
// ---------------------------------------------------------------------------
__global__ __launch_bounds__(256) void prep_w_kernel(
    const float* __restrict__ Wq, const float* __restrict__ Wk, const float* __restrict__ Wv)
{
    const int which = blockIdx.y;
    const float* W = (which == 0) ? Wq : (which == 1) ? Wk : Wv;
    int idx = blockIdx.x * 256 + threadIdx.x;
    float4 v = *(const float4*)(W + (size_t)idx * 4);
    __nv_bfloat16 h0,h1,h2,h3,l0,l1,l2,l3;
    split2(v.x, h0, l0); split2(v.y, h1, l1);
    split2(v.z, h2, l2); split2(v.w, h3, l3);
    *(uint2*)(&g_w_hi[which][(size_t)idx * 4]) = make_uint2(pack2(h0,h1), pack2(h2,h3));
    *(uint2*)(&g_w_lo[which][(size_t)idx * 4]) = make_uint2(pack2(l0,l1), pack2(l2,l3));
}

// ---------------------------------------------------------------------------
// Prep 2: transpose + split x[b][c][n] -> xt[b][n][c] hi/lo. 32x32 tiles.
// ---------------------------------------------------------------------------
__global__ __launch_bounds__(256) void prep_x_kernel(const float* __restrict__ x)
{
    __shared__ float tile[32][33];
    const int n0 = blockIdx.x * 32;
    const int c0 = blockIdx.y * 32;
    const int b  = blockIdx.z;
    const int tid = threadIdx.x;

    {
        int c  = tid >> 3;
        int n4 = (tid & 7) << 2;
        float4 v = *(const float4*)(x + ((size_t)b * DIM + c0 + c) * SEQ + n0 + n4);
        tile[c][n4 + 0] = v.x; tile[c][n4 + 1] = v.y;
        tile[c][n4 + 2] = v.z; tile[c][n4 + 3] = v.w;
    }
    __syncthreads();
    {
        int n  = tid >> 3;
        int c4 = (tid & 7) << 2;
        float f0 = tile[c4 + 0][n], f1 = tile[c4 + 1][n];
        float f2 = tile[c4 + 2][n], f3 = tile[c4 + 3][n];
        __nv_bfloat16 h0,h1,h2,h3,l0,l1,l2,l3;
        split2(f0, h0, l0); split2(f1, h1, l1);
        split2(f2, h2, l2); split2(f3, h3, l3);
        size_t off = ((size_t)b * SEQ + n0 + n) * DIM + c0 + c4;
        *(uint2*)(g_xt_hi + off) = make_uint2(pack2(h0,h1), pack2(h2,h3));
        *(uint2*)(g_xt_lo + off) = make_uint2(pack2(l0,l1), pack2(l2,l3));
    }
}

// ---------------------------------------------------------------------------
// Kernel 1: QKV projection (bf16 3-term).
//   q,k -> [b][n][d] bf16 hi/lo;  v -> TRANSPOSED vt[b][d][n] single fp16.
// grid (SEQ/128 n, DIM/256 d, 3*BATCH), block 256
// ---------------------------------------------------------------------------
constexpr int VSTRIDE = 136;   // fp32 words per staged d-row

__global__ __launch_bounds__(256) void qkv_kernel(
    const float* __restrict__ bq, const float* __restrict__ bk, const float* __restrict__ bv)
{
    extern __shared__ char smem[];
    const uint32_t sb = smem_to_u32(smem);
    const int tid = threadIdx.x;
    const int z = blockIdx.z, which = z >> 3, b = z & 7;
    const float* bias = (which == 0) ? bq : (which == 1) ? bk : bv;

    const int n0 = blockIdx.x * 128;
    const int d0 = blockIdx.y * 256;

    const __nv_bfloat16* aH = g_xt_hi + ((size_t)b * SEQ + n0) * DIM;
    const __nv_bfloat16* aL = g_xt_lo + ((size_t)b * SEQ + n0) * DIM;
    const __nv_bfloat16* bH = &g_w_hi[which][(size_t)d0 * DIM];
    const __nv_bfloat16* bL = &g_w_lo[which][(size_t)d0 * DIM];

    float acc[4][8][4] = {};
    gemm_pipeline(sb, acc, aH, aL, DIM, bH, bL, DIM, DIM / 64, tid);

    const int lane = tid & 31, wid = tid >> 5;
    const int g = lane >> 2, t = lane & 3;
    const int wm = (wid & 1) * 64, wn = (wid >> 1) * 64;

    if (which < 2) {
        __nv_bfloat16* out_hi = (which == 0) ? g_q_hi : g_k_hi;
        __nv_bfloat16* out_lo = (which == 0) ? g_q_lo : g_k_lo;
        #pragma unroll
        for (int tn = 0; tn < 8; tn++) {
            const int d = d0 + wn + tn * 8 + t * 2;
            const float b0 = bias[d], b1 = bias[d + 1];
            #pragma unroll
            for (int tm = 0; tm < 4; tm++)
                #pragma unroll
                for (int h = 0; h < 2; h++) {
                    int n = n0 + wm + tm * 16 + g + h * 8;
                    float f0 = acc[tm][tn][2 * h + 0] + b0;
                    float f1 = acc[tm][tn][2 * h + 1] + b1;
                    __nv_bfloat16 h0, l0, h1, l1;
                    split2(f0, h0, l0); split2(f1, h1, l1);
                    size_t off = ((size_t)b * SEQ + n) * DIM + d;
                    *(uint32_t*)(out_hi + off) = pack2(h0, h1);
                    *(uint32_t*)(out_lo + off) = pack2(l0, l1);
                }
        }
    } else {
        // V: stage fp32 tile [256 d][128 n] in pipeline smem, emit fp16 rows.
        float* stage = (float*)smem;
        #pragma unroll
        for (int tn = 0; tn < 8; tn++) {
            const int dl = wn + tn * 8 + t * 2;
            const float b0 = bias[d0 + dl], b1 = bias[d0 + dl + 1];
            #pragma unroll
            for (int tm = 0; tm < 4; tm++)
                #pragma unroll
                for (int h = 0; h < 2; h++) {
                    int nl = wm + tm * 16 + g + h * 8;
                    stage[(size_t)dl * VSTRIDE + nl]       = acc[tm][tn][2 * h + 0] + b0;
                    stage[(size_t)(dl + 1) * VSTRIDE + nl] = acc[tm][tn][2 * h + 1] + b1;
                }
        }
        __syncthreads();
        #pragma unroll
        for (int i = 0; i < 8; i++) {
            int row = i * 32 + (tid >> 3);       // 0..255 (d-local)
            int col = (tid & 7) * 16;            // 0..112 (n-local)
            const float* src = stage + (size_t)row * VSTRIDE + col;
            __half eh[16];
            #pragma unroll
            for (int j = 0; j < 16; j += 4) {
                float4 v = *(const float4*)(src + j);
                eh[j+0] = __float2half(v.x); eh[j+1] = __float2half(v.y);
                eh[j+2] = __float2half(v.z); eh[j+3] = __float2half(v.w);
            }
            size_t off = ((size_t)b * DIM + d0 + row) * SEQ + n0 + col;
            *(uint4*)(g_vt + off)     = *(uint4*)(eh);
            *(uint4*)(g_vt + off + 8) = *(uint4*)(eh + 8);
        }
    }
}

// ---------------------------------------------------------------------------
// Kernel 2: scores (bf16 3-term).  grid (SEQ/256 m, SEQ/128 n, BATCH).
// ---------------------------------------------------------------------------
__global__ __launch_bounds__(256) void scores_kernel()
{
    extern __shared__ char smem[];
    const uint32_t sb = smem_to_u32(smem);
    const int tid = threadIdx.x;
    const int b  = blockIdx.z;
    const int m0 = blockIdx.x * 256;
    const int n0 = blockIdx.y * 128;

    const __nv_bfloat16* aH = g_q_hi + ((size_t)b * SEQ + n0) * DIM;
    const __nv_bfloat16* aL = g_q_lo + ((size_t)b * SEQ + n0) * DIM;
    const __nv_bfloat16* bH = g_k_hi + ((size_t)b * SEQ + m0) * DIM;
    const __nv_bfloat16* bL = g_k_lo + ((size_t)b * SEQ + m0) * DIM;

    float acc[4][8][4] = {};
    gemm_pipeline(sb, acc, aH, aL, DIM, bH, bL, DIM, DIM / 64, tid);

    const int lane = tid & 31, wid = tid >> 5;
    const int g = lane >> 2, t = lane & 3;
    const int wm = (wid & 1) * 64, wn = (wid >> 1) * 64;
    float* S = g_scores + (size_t)b * SEQ * SEQ;
    #pragma unroll
    for (int tm = 0; tm < 4; tm++)
        #pragma unroll
        for (int h = 0; h < 2; h++) {
            int n = n0 + wm + tm * 16 + g + h * 8;
            #pragma unroll
            for (int tn = 0; tn < 8; tn++) {
                int m = m0 + wn + tn * 8 + t * 2;
                float2 v = make_float2(acc[tm][tn][2 * h], acc[tm][tn][2 * h + 1]);
                *(float2*)(S + (size_t)n * SEQ + m) = v;
            }
        }
}

// ---------------------------------------------------------------------------
// Kernel 3: row softmax (vectorized); fp32 scores in, split fp16 P out.
// ---------------------------------------------------------------------------
__global__ __launch_bounds__(256) void softmax_kernel()
{
    const int row = blockIdx.x;
    const float* p = g_scores + (size_t)row * SEQ;
    const int t = threadIdx.x;

    float v[8];
    {
        float4 a = *(const float4*)(p + t * 4);
        float4 b = *(const float4*)(p + 1024 + t * 4);
        v[0]=a.x; v[1]=a.y; v[2]=a.z; v[3]=a.w;
        v[4]=b.x; v[5]=b.y; v[6]=b.z; v[7]=b.w;
    }
    float mx = v[0];
    #pragma unroll
    for (int i = 1; i < 8; i++) mx = fmaxf(mx, v[i]);

    __shared__ float red[8];
    #pragma unroll
    for (int o = 16; o > 0; o >>= 1) mx = fmaxf(mx, __shfl_xor_sync(0xffffffffu, mx, o));
    if ((t & 31) == 0) red[t >> 5] = mx;
    __syncthreads();
    mx = red[0];
    #pragma unroll
    for (int w = 1; w < 8; w++) mx = fmaxf(mx, red[w]);
    __syncthreads();

    float s = 0.f;
    #pragma unroll
    for (int i = 0; i < 8; i++) { v[i] = __expf(v[i] - mx); s += v[i]; }
    #pragma unroll
    for (int o = 16; o > 0; o >>= 1) s += __shfl_xor_sync(0xffffffffu, s, o);
    if ((t & 31) == 0) red[t >> 5] = s;
    __syncthreads();
    s = red[0];
    #pragma unroll
    for (int w = 1; w < 8; w++) s += red[w];

    const float inv = 1.0f / s;
    __half h[8], l[8];
    #pragma unroll
    for (int i = 0; i < 8; i++) split2h(v[i] * inv, h[i], l[i]);

    size_t base = (size_t)row * SEQ;
    *(uint2*)(g_p_hi + base + t * 4)        = make_uint2(pack2h(h[0],h[1]), pack2h(h[2],h[3]));
    *(uint2*)(g_p_hi + base + 1024 + t * 4) = make_uint2(pack2h(h[4],h[5]), pack2h(h[6],h[7]));
    *(uint2*)(g_p_lo + base + t * 4)        = make_uint2(pack2h(l[0],l[1]), pack2h(l[2],l[3]));
    *(uint2*)(g_p_lo + base + 1024 + t * 4) = make_uint2(pack2h(l[4],l[5]), pack2h(l[6],l[7]));
}

// ---------------------------------------------------------------------------
// Kernel 4: out[b][d][n] = sum_m vt[d][m] * (pH + pL)[n][m]   (fp16 2-term)
// grid (SEQ/256 n, DIM/128 d, BATCH), block 256
// ---------------------------------------------------------------------------
__global__ __launch_bounds__(256) void pv_kernel(float* __restrict__ out)
{
    extern __shared__ char smem[];
    const uint32_t sb = smem_to_u32(smem);
    const int tid = threadIdx.x;
    const int b  = blockIdx.z;
    const int n0 = blockIdx.x * 256;
    const int d0 = blockIdx.y * 128;

    const __half* a  = g_vt   + ((size_t)b * DIM + d0) * SEQ;
    const __half* bH = g_p_hi + ((size_t)b * SEQ + n0) * SEQ;
    const __half* bL = g_p_lo + ((size_t)b * SEQ + n0) * SEQ;

    float acc[4][8][4] = {};
    pv_pipeline(sb, acc, a, SEQ, bH, bL, SEQ, SEQ / 64, tid);

    const int lane = tid & 31, wid = tid >> 5;
    const int g = lane >> 2, t = lane & 3;
    const int wm = (wid & 1) * 64, wn = (wid >> 1) * 64;
    float* ob = out + (size_t)b * DIM * SEQ;
    #pragma unroll
    for (int tm = 0; tm < 4; tm++)
        #pragma unroll
        for (int h = 0; h < 2; h++) {
            int d = d0 + wm + tm * 16 + g + h * 8;
            #pragma unroll
            for (int tn = 0; tn < 8; tn++) {
                int n = n0 + wn + tn * 8 + t * 2;
                float2 v = make_float2(acc[tm][tn][2 * h], acc[tm][tn][2 * h + 1]);
                *(float2*)(ob + (size_t)d * SEQ + n) = v;
            }
        }
}

// ---------------------------------------------------------------------------
extern "C" void kernel_launch(void* const* d_in, const int* in_sizes, int n_in,
                              void* d_out, int out_size)
{
    (void)in_sizes; (void)n_in; (void)out_size;
    const float* x  = (const float*)d_in[0];
    const float* Wq = (const float*)d_in[1];
    const float* bq = (const float*)d_in[2];
    const float* Wk = (const float*)d_in[3];
    const float* bk = (const float*)d_in[4];
    const float* Wv = (const float*)d_in[5];
    const float* bv = (const float*)d_in[6];
    float* out = (float*)d_out;

    cudaFuncSetAttribute(qkv_kernel,    cudaFuncAttributeMaxDynamicSharedMemorySize, SMEM_BYTES);
    cudaFuncSetAttribute(scores_kernel, cudaFuncAttributeMaxDynamicSharedMemorySize, SMEM_BYTES);
    cudaFuncSetAttribute(pv_kernel,     cudaFuncAttributeMaxDynamicSharedMemorySize, PV_SMEM_BYTES);

    prep_w_kernel<<<dim3(256, 3), 256>>>(Wq, Wk, Wv);
    prep_x_kernel<<<dim3(SEQ / 32, DIM / 32, BATCH), 256>>>(x);
    qkv_kernel<<<dim3(SEQ / 128, DIM / 256, 3 * BATCH), 256, SMEM_BYTES>>>(bq, bk, bv);
    scores_kernel<<<dim3(SEQ / 256, SEQ / 128, BATCH), 256, SMEM_BYTES>>>();
    softmax_kernel<<<BATCH * SEQ, 256>>>();
    pv_kernel<<<dim3(SEQ / 256, DIM / 128, BATCH), 256, PV_SMEM_BYTES>>>(out);
}

// round 17
// speedup vs baseline: 1.6779x; 1.1231x over previous
#include <cuda_runtime.h>
#include <cuda_bf16.h>
#include <cuda_fp16.h>
#include <cstdint>
#include <math_constants.h>

constexpr int BATCH = 8;
constexpr int DIM   = 512;
constexpr int SEQ   = 2048;

// ---------------------------------------------------------------------------
// Scratch (device globals; no allocation allowed)
// ---------------------------------------------------------------------------
__device__ __align__(128) __nv_bfloat16 g_xt_hi[(size_t)BATCH * SEQ * DIM]; // [b][n][c]
__device__ __align__(128) __nv_bfloat16 g_xt_lo[(size_t)BATCH * SEQ * DIM];
__device__ __align__(128) __nv_bfloat16 g_w_hi[3][(size_t)DIM * DIM];      // [which][d][c]
__device__ __align__(128) __nv_bfloat16 g_w_lo[3][(size_t)DIM * DIM];
__device__ __align__(128) __nv_bfloat16 g_q_hi[(size_t)BATCH * SEQ * DIM]; // [b][n][d]
__device__ __align__(128) __nv_bfloat16 g_q_lo[(size_t)BATCH * SEQ * DIM];
__device__ __align__(128) __nv_bfloat16 g_k_hi[(size_t)BATCH * SEQ * DIM];
__device__ __align__(128) __nv_bfloat16 g_k_lo[(size_t)BATCH * SEQ * DIM];
__device__ __align__(128) __half        g_vt   [(size_t)BATCH * DIM * SEQ]; // [b][d][m] fp16
__device__ __align__(128) float         g_scores[(size_t)BATCH * SEQ * SEQ];
__device__ __align__(128) __half        g_p    [(size_t)BATCH * SEQ * SEQ]; // [b][n][m] fp16
 
// ---------------------------------------------------------------------------
// Helpers
// ---------------------------------------------------------------------------
__device__ __forceinline__ uint32_t smem_to_u32(const void* p) {
    uint32_t a;
    asm("{ .reg .u64 t; cvta.to.shared.u64 t, %1; cvt.u32.u64 %0, t; }" : "=r"(a) : "l"(p));
    return a;
}
#define SWZ(x) ((x) ^ (((x) >> 3) & 0x70))

__device__ __forceinline__ void split2(float f, __nv_bfloat16& h, __nv_bfloat16& l) {
    h = __float2bfloat16(f);
    l = __float2bfloat16(f - __bfloat162float(h));
}
__device__ __forceinline__ uint32_t pack2(__nv_bfloat16 a, __nv_bfloat16 b) {
    __nv_bfloat162 t = __halves2bfloat162(a, b);
    return *reinterpret_cast<uint32_t*>(&t);
}
__device__ __forceinline__ uint32_t pack2h(__half a, __half b) {
    __half2 t = __halves2half2(a, b);
    return *reinterpret_cast<uint32_t*>(&t);
}

__device__ __forceinline__ void ldsm_x4(uint32_t* r, uint32_t addr) {
    asm volatile("ldmatrix.sync.aligned.m8n8.x4.shared.b16 {%0,%1,%2,%3}, [%4];"
        : "=r"(r[0]), "=r"(r[1]), "=r"(r[2]), "=r"(r[3]) : "r"(addr));
}
__device__ __forceinline__ void mma16816(float* c, const uint32_t* a, const uint32_t* b) {
    asm volatile(
        "mma.sync.aligned.m16n8k16.row.col.f32.bf16.bf16.f32 "
        "{%0,%1,%2,%3}, {%4,%5,%6,%7}, {%8,%9}, {%0,%1,%2,%3};"
        : "+f"(c[0]), "+f"(c[1]), "+f"(c[2]), "+f"(c[3])
        : "r"(a[0]), "r"(a[1]), "r"(a[2]), "r"(a[3]), "r"(b[0]), "r"(b[1]));
}
__device__ __forceinline__ void mma16816h(float* c, const uint32_t* a, const uint32_t* b) {
    asm volatile(
        "mma.sync.aligned.m16n8k16.row.col.f32.f16.f16.f32 "
        "{%0,%1,%2,%3}, {%4,%5,%6,%7}, {%8,%9}, {%0,%1,%2,%3};"
        : "+f"(c[0]), "+f"(c[1]), "+f"(c[2]), "+f"(c[3])
        : "r"(a[0]), "r"(a[1]), "r"(a[2]), "r"(a[3]), "r"(b[0]), "r"(b[1]));
}
__device__ __forceinline__ void cp16(uint32_t dst, const void* src) {
    asm volatile("cp.async.cg.shared.global [%0], [%1], 16;" :: "r"(dst), "l"(src));
}
#define CP_COMMIT() asm volatile("cp.async.commit_group;" ::: "memory")
#define CP_WAIT1()  asm volatile("cp.async.wait_group 1;" ::: "memory")
#define CP_WAIT0()  asm volatile("cp.async.wait_group 0;" ::: "memory")

// ---------------------------------------------------------------------------
// bf16 3-term path (qkv, scores): CTA 128(M) x 256(N), K-chunk 64, 2-stage.
// ---------------------------------------------------------------------------
constexpr int OFF_AH = 0;
constexpr int OFF_AL = 16384;
constexpr int OFF_BH = 32768;
constexpr int OFF_BL = 65536;
constexpr int STAGE_BYTES = 98304;
constexpr int SMEM_BYTES  = 2 * STAGE_BYTES;  // 192 KB

__device__ __forceinline__ void load_stage(uint32_t st,
    const __nv_bfloat16* aH, const __nv_bfloat16* aL, int strideA,
    const __nv_bfloat16* bH, const __nv_bfloat16* bL, int strideB,
    int k0, int tid)
{
    #pragma unroll
    for (int i = 0; i < 4; i++) {
        int idx = tid + i * 256;
        int r   = idx >> 3;
        int c8  = (idx & 7) << 3;
        uint32_t sw = SWZ((uint32_t)(r * 128 + c8 * 2));
        size_t ga = (size_t)r * strideA + k0 + c8;
        cp16(st + OFF_AH + sw, aH + ga);
        cp16(st + OFF_AL + sw, aL + ga);
    }
    #pragma unroll
    for (int i = 0; i < 8; i++) {
        int idx = tid + i * 256;
        int r   = idx >> 3;
        int c8  = (idx & 7) << 3;
        uint32_t sw = SWZ((uint32_t)(r * 128 + c8 * 2));
        size_t gb = (size_t)r * strideB + k0 + c8;
        cp16(st + OFF_BH + sw, bH + gb);
        cp16(st + OFF_BL + sw, bL + gb);
    }
}

// acc += AH*BH + AL*BH + AH*BL  (R7-proven ordering)
__device__ __forceinline__ void mma_consume(uint32_t st, float acc[4][8][4]) {
    const int lane = threadIdx.x & 31;
    const int wid  = threadIdx.x >> 5;
    const int wm   = (wid & 1) * 64;
    const int wn   = (wid >> 1) * 64;

    #pragma unroll
    for (int k16 = 0; k16 < 4; k16++) {
        uint32_t aH[4][4], aL[4][4], B[4][4];
        #pragma unroll
        for (int tm = 0; tm < 4; tm++) {
            int r  = wm + tm * 16 + (lane & 15);
            int ku = k16 * 2 + (lane >> 4);
            uint32_t off = SWZ((uint32_t)(r * 128 + ku * 16));
            ldsm_x4(aH[tm], st + OFF_AH + off);
            ldsm_x4(aL[tm], st + OFF_AL + off);
        }
        #pragma unroll
        for (int tb = 0; tb < 4; tb++) {
            int g  = lane >> 3;
            int r  = wn + tb * 16 + (g >> 1) * 8 + (lane & 7);
            int ku = k16 * 2 + (g & 1);
            ldsm_x4(B[tb], st + OFF_BH + SWZ((uint32_t)(r * 128 + ku * 16)));
        }
        #pragma unroll
        for (int tm = 0; tm < 4; tm++)
            #pragma unroll
            for (int tn = 0; tn < 8; tn++) {
                uint32_t bf[2];
                bf[0] = B[tn >> 1][(tn & 1) ? 2 : 0];
                bf[1] = B[tn >> 1][(tn & 1) ? 3 : 1];
                mma16816(acc[tm][tn], aH[tm], bf);
                mma16816(acc[tm][tn], aL[tm], bf);
            }
        #pragma unroll
        for (int tb = 0; tb < 4; tb++) {
            int g  = lane >> 3;
            int r  = wn + tb * 16 + (g >> 1) * 8 + (lane & 7);
            int ku = k16 * 2 + (g & 1);
            ldsm_x4(B[tb], st + OFF_BL + SWZ((uint32_t)(r * 128 + ku * 16)));
        }
        #pragma unroll
        for (int tm = 0; tm < 4; tm++)
            #pragma unroll
            for (int tn = 0; tn < 8; tn++) {
                uint32_t bf[2];
                bf[0] = B[tn >> 1][(tn & 1) ? 2 : 0];
                bf[1] = B[tn >> 1][(tn & 1) ? 3 : 1];
                mma16816(acc[tm][tn], aH[tm], bf);
            }
    }
}

__device__ __forceinline__ void gemm_pipeline(uint32_t sb, float acc[4][8][4],
    const __nv_bfloat16* aH, const __nv_bfloat16* aL, int strideA,
    const __nv_bfloat16* bH, const __nv_bfloat16* bL, int strideB,
    int NC, int tid)
{
    load_stage(sb, aH, aL, strideA, bH, bL, strideB, 0, tid);
    CP_COMMIT();
    for (int ch = 0; ch < NC; ++ch) {
        uint32_t cur = sb + (uint32_t)(ch & 1) * STAGE_BYTES;
        if (ch + 1 < NC) {
            uint32_t nxt = sb + (uint32_t)((ch + 1) & 1) * STAGE_BYTES;
            load_stage(nxt, aH, aL, strideA, bH, bL, strideB, (ch + 1) * 64, tid);
            CP_COMMIT();
            CP_WAIT1();
        } else {
            CP_WAIT0();
        }
        __syncthreads();
        mma_consume(cur, acc);
        __syncthreads();
    }
}

// ---------------------------------------------------------------------------
// fp16 1-term PV path: A single (vt fp16), B single (P fp16).
// Per-stage: A 16KB + B 32KB = 48KB; 2 stages = 96KB.
// ---------------------------------------------------------------------------
constexpr int OFF_PA = 0;
constexpr int OFF_PB = 16384;
constexpr int PV_STAGE_BYTES = 49152;
constexpr int PV_SMEM_BYTES  = 2 * PV_STAGE_BYTES;  // 96 KB

__device__ __forceinline__ void load_stage_pv(uint32_t st,
    const __half* a, int strideA,
    const __half* b, int strideB,
    int k0, int tid)
{
    #pragma unroll
    for (int i = 0; i < 4; i++) {
        int idx = tid + i * 256;
        int r   = idx >> 3;
        int c8  = (idx & 7) << 3;
        uint32_t sw = SWZ((uint32_t)(r * 128 + c8 * 2));
        cp16(st + OFF_PA + sw, a + (size_t)r * strideA + k0 + c8);
    }
    #pragma unroll
    for (int i = 0; i < 8; i++) {
        int idx = tid + i * 256;
        int r   = idx >> 3;
        int c8  = (idx & 7) << 3;
        uint32_t sw = SWZ((uint32_t)(r * 128 + c8 * 2));
        cp16(st + OFF_PB + sw, b + (size_t)r * strideB + k0 + c8);
    }
}

// acc += A*B   (fp16 single-term)
__device__ __forceinline__ void mma_consume_pv(uint32_t st, float acc[4][8][4]) {
    const int lane = threadIdx.x & 31;
    const int wid  = threadIdx.x >> 5;
    const int wm   = (wid & 1) * 64;
    const int wn   = (wid >> 1) * 64;

    #pragma unroll
    for (int k16 = 0; k16 < 4; k16++) {
        uint32_t A[4][4], B[4][4];
        #pragma unroll
        for (int tm = 0; tm < 4; tm++) {
            int r  = wm + tm * 16 + (lane & 15);
            int ku = k16 * 2 + (lane >> 4);
            ldsm_x4(A[tm], st + OFF_PA + SWZ((uint32_t)(r * 128 + ku * 16)));
        }
        #pragma unroll
        for (int tb = 0; tb < 4; tb++) {
            int g  = lane >> 3;
            int r  = wn + tb * 16 + (g >> 1) * 8 + (lane & 7);
            int ku = k16 * 2 + (g & 1);
            ldsm_x4(B[tb], st + OFF_PB + SWZ((uint32_t)(r * 128 + ku * 16)));
        }
        #pragma unroll
        for (int tm = 0; tm < 4; tm++)
            #pragma unroll
            for (int tn = 0; tn < 8; tn++) {
                uint32_t bf[2];
                bf[0] = B[tn >> 1][(tn & 1) ? 2 : 0];
                bf[1] = B[tn >> 1][(tn & 1) ? 3 : 1];
                mma16816h(acc[tm][tn], A[tm], bf);
            }
    }
}

__device__ __forceinline__ void pv_pipeline(uint32_t sb, float acc[4][8][4],
    const __half* a, int strideA,
    const __half* b, int strideB,
    int NC, int tid)
{
    load_stage_pv(sb, a, strideA, b, strideB, 0, tid);
    CP_COMMIT();
    for (int ch = 0; ch < NC; ++ch) {
        uint32_t cur = sb + (uint32_t)(ch & 1) * PV_STAGE_BYTES;
        if (ch + 1 < NC) {
            uint32_t nxt = sb + (uint32_t)((ch + 1) & 1) * PV_STAGE_BYTES;
            load_stage_pv(nxt, a, strideA, b, strideB, (ch + 1) * 64, tid);
            CP_COMMIT();
            CP_WAIT1();
        } else {
            CP_WAIT0();
        }
        __syncthreads();
        mma_consume_pv(cur, acc);
        __syncthreads();
    }
}

// ---------------------------------------------------------------------------
// Prep 1: split W into bf16 hi/lo.  grid (256, 3), block 256.
// ---------------------------------------------------------------------------
__global__ __launch_bounds__(256) void prep_w_kernel(
    const float* __restrict__ Wq, const float* __restrict__ Wk, const float* __restrict__ Wv)
{
    const int which = blockIdx.y;
    const float* W = (which == 0) ? Wq : (which == 1) ? Wk : Wv;
    int idx = blockIdx.x * 256 + threadIdx.x;
    float4 v = *(const float4*)(W + (size_t)idx * 4);
    __nv_bfloat16 h0,h1,h2,h3,l0,l1,l2,l3;
    split2(v.x, h0, l0); split2(v.y, h1, l1);
    split2(v.z, h2, l2); split2(v.w, h3, l3);
    *(uint2*)(&g_w_hi[which][(size_t)idx * 4]) = make_uint2(pack2(h0,h1), pack2(h2,h3));
    *(uint2*)(&g_w_lo[which][(size_t)idx * 4]) = make_uint2(pack2(l0,l1), pack2(l2,l3));
}

// ---------------------------------------------------------------------------
// Prep 2: transpose + split x[b][c][n] -> xt[b][n][c] hi/lo. 32x32 tiles.
// ---------------------------------------------------------------------------
__global__ __launch_bounds__(256) void prep_x_kernel(const float* __restrict__ x)
{
    __shared__ float tile[32][33];
    const int n0 = blockIdx.x * 32;
    const int c0 = blockIdx.y * 32;
    const int b  = blockIdx.z;
    const int tid = threadIdx.x;

    {
        int c  = tid >> 3;
        int n4 = (tid & 7) << 2;
        float4 v = *(const float4*)(x + ((size_t)b * DIM + c0 + c) * SEQ + n0 + n4);
        tile[c][n4 + 0] = v.x; tile[c][n4 + 1] = v.y;
        tile[c][n4 + 2] = v.z; tile[c][n4 + 3] = v.w;
    }
    __syncthreads();
    {
        int n  = tid >> 3;
        int c4 = (tid & 7) << 2;
        float f0 = tile[c4 + 0][n], f1 = tile[c4 + 1][n];
        float f2 = tile[c4 + 2][n], f3 = tile[c4 + 3][n];
        __nv_bfloat16 h0,h1,h2,h3,l0,l1,l2,l3;
        split2(f0, h0, l0); split2(f1, h1, l1);
        split2(f2, h2, l2); split2(f3, h3, l3);
        size_t off = ((size_t)b * SEQ + n0 + n) * DIM + c0 + c4;
        *(uint2*)(g_xt_hi + off) = make_uint2(pack2(h0,h1), pack2(h2,h3));
        *(uint2*)(g_xt_lo + off) = make_uint2(pack2(l0,l1), pack2(l2,l3));
    }
}

// ---------------------------------------------------------------------------
// Kernel 1: QKV projection (bf16 3-term).
//   q,k -> [b][n][d] bf16 hi/lo;  v -> TRANSPOSED vt[b][d][n] single fp16.
// grid (SEQ/128 n, DIM/256 d, 3*BATCH), block 256
// ---------------------------------------------------------------------------
constexpr int VSTRIDE = 136;   // fp32 words per staged d-row

__global__ __launch_bounds__(256) void qkv_kernel(
    const float* __restrict__ bq, const float* __restrict__ bk, const float* __restrict__ bv)
{
    extern __shared__ char smem[];
    const uint32_t sb = smem_to_u32(smem);
    const int tid = threadIdx.x;
    const int z = blockIdx.z, which = z >> 3, b = z & 7;
    const float* bias = (which == 0) ? bq : (which == 1) ? bk : bv;

    const int n0 = blockIdx.x * 128;
    const int d0 = blockIdx.y * 256;

    const __nv_bfloat16* aH = g_xt_hi + ((size_t)b * SEQ + n0) * DIM;
    const __nv_bfloat16* aL = g_xt_lo + ((size_t)b * SEQ + n0) * DIM;
    const __nv_bfloat16* bH = &g_w_hi[which][(size_t)d0 * DIM];
    const __nv_bfloat16* bL = &g_w_lo[which][(size_t)d0 * DIM];

    float acc[4][8][4] = {};
    gemm_pipeline(sb, acc, aH, aL, DIM, bH, bL, DIM, DIM / 64, tid);

    const int lane = tid & 31, wid = tid >> 5;
    const int g = lane >> 2, t = lane & 3;
    const int wm = (wid & 1) * 64, wn = (wid >> 1) * 64;

    if (which < 2) {
        __nv_bfloat16* out_hi = (which == 0) ? g_q_hi : g_k_hi;
        __nv_bfloat16* out_lo = (which == 0) ? g_q_lo : g_k_lo;
        #pragma unroll
        for (int tn = 0; tn < 8; tn++) {
            const int d = d0 + wn + tn * 8 + t * 2;
            const float b0 = bias[d], b1 = bias[d + 1];
            #pragma unroll
            for (int tm = 0; tm < 4; tm++)
                #pragma unroll
                for (int h = 0; h < 2; h++) {
                    int n = n0 + wm + tm * 16 + g + h * 8;
                    float f0 = acc[tm][tn][2 * h + 0] + b0;
                    float f1 = acc[tm][tn][2 * h + 1] + b1;
                    __nv_bfloat16 h0, l0, h1, l1;
                    split2(f0, h0, l0); split2(f1, h1, l1);
                    size_t off = ((size_t)b * SEQ + n) * DIM + d;
                    *(uint32_t*)(out_hi + off) = pack2(h0, h1);
                    *(uint32_t*)(out_lo + off) = pack2(l0, l1);
                }
        }
    } else {
        // V: stage fp32 tile [256 d][128 n] in pipeline smem, emit fp16 rows.
        float* stage = (float*)smem;
        #pragma unroll
        for (int tn = 0; tn < 8; tn++) {
            const int dl = wn + tn * 8 + t * 2;
            const float b0 = bias[d0 + dl], b1 = bias[d0 + dl + 1];
            #pragma unroll
            for (int tm = 0; tm < 4; tm++)
                #pragma unroll
                for (int h = 0; h < 2; h++) {
                    int nl = wm + tm * 16 + g + h * 8;
                    stage[(size_t)dl * VSTRIDE + nl]       = acc[tm][tn][2 * h + 0] + b0;
                    stage[(size_t)(dl + 1) * VSTRIDE + nl] = acc[tm][tn][2 * h + 1] + b1;
                }
        }
        __syncthreads();
        #pragma unroll
        for (int i = 0; i < 8; i++) {
            int row = i * 32 + (tid >> 3);       // 0..255 (d-local)
            int col = (tid & 7) * 16;            // 0..112 (n-local)
            const float* src = stage + (size_t)row * VSTRIDE + col;
            __half eh[16];
            #pragma unroll
            for (int j = 0; j < 16; j += 4) {
                float4 v = *(const float4*)(src + j);
                eh[j+0] = __float2half(v.x); eh[j+1] = __float2half(v.y);
                eh[j+2] = __float2half(v.z); eh[j+3] = __float2half(v.w);
            }
            size_t off = ((size_t)b * DIM + d0 + row) * SEQ + n0 + col;
            *(uint4*)(g_vt + off)     = *(uint4*)(eh);
            *(uint4*)(g_vt + off + 8) = *(uint4*)(eh + 8);
        }
    }
}

// ---------------------------------------------------------------------------
// Kernel 2: scores (bf16 3-term).  grid (SEQ/256 m, SEQ/128 n, BATCH).
// ---------------------------------------------------------------------------
__global__ __launch_bounds__(256) void scores_kernel()
{
    extern __shared__ char smem[];
    const uint32_t sb = smem_to_u32(smem);
    const int tid = threadIdx.x;
    const int b  = blockIdx.z;
    const int m0 = blockIdx.x * 256;
    const int n0 = blockIdx.y * 128;

    const __nv_bfloat16* aH = g_q_hi + ((size_t)b * SEQ + n0) * DIM;
    const __nv_bfloat16* aL = g_q_lo + ((size_t)b * SEQ + n0) * DIM;
    const __nv_bfloat16* bH = g_k_hi + ((size_t)b * SEQ + m0) * DIM;
    const __nv_bfloat16* bL = g_k_lo + ((size_t)b * SEQ + m0) * DIM;

    float acc[4][8][4] = {};
    gemm_pipeline(sb, acc, aH, aL, DIM, bH, bL, DIM, DIM / 64, tid);

    const int lane = tid & 31, wid = tid >> 5;
    const int g = lane >> 2, t = lane & 3;
    const int wm = (wid & 1) * 64, wn = (wid >> 1) * 64;
    float* S = g_scores + (size_t)b * SEQ * SEQ;
    #pragma unroll
    for (int tm = 0; tm < 4; tm++)
        #pragma unroll
        for (int h = 0; h < 2; h++) {
            int n = n0 + wm + tm * 16 + g + h * 8;
            #pragma unroll
            for (int tn = 0; tn < 8; tn++) {
                int m = m0 + wn + tn * 8 + t * 2;
                float2 v = make_float2(acc[tm][tn][2 * h], acc[tm][tn][2 * h + 1]);
                *(float2*)(S + (size_t)n * SEQ + m) = v;
            }
        }
}

// ---------------------------------------------------------------------------
// Kernel 3: row softmax (vectorized); fp32 scores in, single fp16 P out.
// ---------------------------------------------------------------------------
__global__ __launch_bounds__(256) void softmax_kernel()
{
    const int row = blockIdx.x;
    const float* p = g_scores + (size_t)row * SEQ;
    const int t = threadIdx.x;

    float v[8];
    {
        float4 a = *(const float4*)(p + t * 4);
        float4 b = *(const float4*)(p + 1024 + t * 4);
        v[0]=a.x; v[1]=a.y; v[2]=a.z; v[3]=a.w;
        v[4]=b.x; v[5]=b.y; v[6]=b.z; v[7]=b.w;
    }
    float mx = v[0];
    #pragma unroll
    for (int i = 1; i < 8; i++) mx = fmaxf(mx, v[i]);

    __shared__ float red[8];
    #pragma unroll
    for (int o = 16; o > 0; o >>= 1) mx = fmaxf(mx, __shfl_xor_sync(0xffffffffu, mx, o));
    if ((t & 31) == 0) red[t >> 5] = mx;
    __syncthreads();
    mx = red[0];
    #pragma unroll
    for (int w = 1; w < 8; w++) mx = fmaxf(mx, red[w]);
    __syncthreads();

    float s = 0.f;
    #pragma unroll
    for (int i = 0; i < 8; i++) { v[i] = __expf(v[i] - mx); s += v[i]; }
    #pragma unroll
    for (int o = 16; o > 0; o >>= 1) s += __shfl_xor_sync(0xffffffffu, s, o);
    if ((t & 31) == 0) red[t >> 5] = s;
    __syncthreads();
    s = red[0];
    #pragma unroll
    for (int w = 1; w < 8; w++) s += red[w];

    const float inv = 1.0f / s;
    __half h[8];
    #pragma unroll
    for (int i = 0; i < 8; i++) h[i] = __float2half(v[i] * inv);

    size_t base = (size_t)row * SEQ;
    *(uint2*)(g_p + base + t * 4)        = make_uint2(pack2h(h[0],h[1]), pack2h(h[2],h[3]));
    *(uint2*)(g_p + base + 1024 + t * 4) = make_uint2(pack2h(h[4],h[5]), pack2h(h[6],h[7]));
}

// ---------------------------------------------------------------------------
// Kernel 4: out[b][d][n] = sum_m vt[d][m] * p[n][m]   (fp16 1-term)
// grid (SEQ/256 n, DIM/128 d, BATCH), block 256
// ---------------------------------------------------------------------------
__global__ __launch_bounds__(256) void pv_kernel(float* __restrict__ out)
{
    extern __shared__ char smem[];
    const uint32_t sb = smem_to_u32(smem);
    const int tid = threadIdx.x;
    const int b  = blockIdx.z;
    const int n0 = blockIdx.x * 256;
    const int d0 = blockIdx.y * 128;

    const __half* a  = g_vt + ((size_t)b * DIM + d0) * SEQ;
    const __half* bp = g_p  + ((size_t)b * SEQ + n0) * SEQ;

    float acc[4][8][4] = {};
    pv_pipeline(sb, acc, a, SEQ, bp, SEQ, SEQ / 64, tid);

    const int lane = tid & 31, wid = tid >> 5;
    const int g = lane >> 2, t = lane & 3;
    const int wm = (wid & 1) * 64, wn = (wid >> 1) * 64;
    float* ob = out + (size_t)b * DIM * SEQ;
    #pragma unroll
    for (int tm = 0; tm < 4; tm++)
        #pragma unroll
        for (int h = 0; h < 2; h++) {
            int d = d0 + wm + tm * 16 + g + h * 8;
            #pragma unroll
            for (int tn = 0; tn < 8; tn++) {
                int n = n0 + wn + tn * 8 + t * 2;
                float2 v = make_float2(acc[tm][tn][2 * h], acc[tm][tn][2 * h + 1]);
                *(float2*)(ob + (size_t)d * SEQ + n) = v;
            }
        }
}

// ---------------------------------------------------------------------------
extern "C" void kernel_launch(void* const* d_in, const int* in_sizes, int n_in,
                              void* d_out, int out_size)
{
    (void)in_sizes; (void)n_in; (void)out_size;
    const float* x  = (const float*)d_in[0];
    const float* Wq = (const float*)d_in[1];
    const float* bq = (const float*)d_in[2];
    const float* Wk = (const float*)d_in[3];
    const float* bk = (const float*)d_in[4];
    const float* Wv = (const float*)d_in[5];
    const float* bv = (const float*)d_in[6];
    float* out = (float*)d_out;

    cudaFuncSetAttribute(qkv_kernel,    cudaFuncAttributeMaxDynamicSharedMemorySize, SMEM_BYTES);
    cudaFuncSetAttribute(scores_kernel, cudaFuncAttributeMaxDynamicSharedMemorySize, SMEM_BYTES);
    cudaFuncSetAttribute(pv_kernel,     cudaFuncAttributeMaxDynamicSharedMemorySize, PV_SMEM_BYTES);

    prep_w_kernel<<<dim3(256, 3), 256>>>(Wq, Wk, Wv);
    prep_x_kernel<<<dim3(SEQ / 32, DIM / 32, BATCH), 256>>>(x);
    qkv_kernel<<<dim3(SEQ / 128, DIM / 256, 3 * BATCH), 256, SMEM_BYTES>>>(bq, bk, bv);
    scores_kernel<<<dim3(SEQ / 256, SEQ / 128, BATCH), 256, SMEM_BYTES>>>();
    softmax_kernel<<<BATCH * SEQ, 256>>>();
    pv_kernel<<<dim3(SEQ / 256, DIM / 128, BATCH), 256, PV_SMEM_BYTES>>>(out);
}